// round 1
// baseline (speedup 1.0000x reference)
#include <cuda_runtime.h>

#define N_TOTAL 100000
#define B_TOTAL 2048
#define F_DIM 16
#define D_DIM 64
#define NCH 32
#define NTILES ((N_TOTAL + 63) >> 6)   // 1563

// Scratch (allocation-free): precomputed scaled squared norms + deterministic partials
__device__ float g_xsqs[N_TOTAL];
__device__ float g_zsqs[B_TOTAL];
__device__ float g_part[NCH * B_TOTAL * F_DIM];

typedef unsigned long long u64;

__device__ __forceinline__ u64 fma2(u64 a, u64 b, u64 c) {
    u64 d;
    asm("fma.rn.f32x2 %0, %1, %2, %3;" : "=l"(d) : "l"(a), "l"(b), "l"(c));
    return d;
}
__device__ __forceinline__ u64 pack2(float lo, float hi) {
    u64 d;
    asm("mov.b64 %0, {%1, %2};" : "=l"(d) : "f"(lo), "f"(hi));
    return d;
}
__device__ __forceinline__ void unpack2(u64 v, float& lo, float& hi) {
    asm("mov.b64 {%0, %1}, %2;" : "=f"(lo), "=f"(hi) : "l"(v));
}

// Prologue: scaled squared norms. One warp per row (coalesced 64-float row read).
__global__ void rbf_pre(const float* __restrict__ z, const float* __restrict__ dataset) {
    int w = (blockIdx.x * blockDim.x + threadIdx.x) >> 5;
    int lane = threadIdx.x & 31;
    const float* src;
    float* dst;
    if (w < N_TOTAL) {
        src = dataset + (size_t)w * D_DIM;
        dst = g_xsqs + w;
    } else if (w < N_TOTAL + B_TOTAL) {
        src = z + (size_t)(w - N_TOTAL) * D_DIM;
        dst = g_zsqs + (w - N_TOTAL);
    } else {
        return;
    }
    float a = src[lane];
    float b = src[lane + 32];
    float s = a * a + b * b;
    #pragma unroll
    for (int o = 16; o; o >>= 1) s += __shfl_xor_sync(0xffffffffu, s, o);
    // pre-scale by 1/(2*ln2) so:  exp(-sq/2) = exp2f(cross*log2e - zs - xs)
    if (lane == 0) *dst = s * 0.72134752044448170f;
}

// Main fused kernel: 64(b) x 64(n) tile per block, 16x16 threads, 4x4 micro-tile.
// grid = (B/64, NCH); block (bx, cz) accumulates over n-tiles t = cz, cz+NCH, ...
__global__ void __launch_bounds__(256, 2)
rbf_main(const float* __restrict__ z, const float* __restrict__ dataset,
         const float* __restrict__ alpha) {
    // transposed (d-major) tiles; stride 66 keeps 8B alignment for float2 LDS
    // and gives only 2-way bank conflicts.
    __shared__ __align__(16) float zt[D_DIM][66];
    __shared__ __align__(16) float xt[D_DIM][66];
    __shared__ __align__(16) float at[64][18];   // alpha tile [n][f], pad->18
    __shared__ float zs_s[64];
    __shared__ float xs_s[64];

    const int tid = threadIdx.x;
    const int tx = tid & 15;
    const int ty = tid >> 4;
    const int b0 = blockIdx.x << 6;

    // Load z tile once (transposed). Global read coalesced along d.
    #pragma unroll
    for (int i = 0; i < 16; i++) {
        int e = tid + i * 256;
        int r = e >> 6, d = e & 63;
        zt[d][r] = z[(size_t)(b0 + r) * D_DIM + d];
    }
    if (tid < 64) zs_s[tid] = g_zsqs[b0 + tid];

    // Packed accumulators: 4 b-rows x 16 f (as 8 f32x2 pairs)
    u64 acc2[4][8];
    #pragma unroll
    for (int i = 0; i < 4; i++)
        #pragma unroll
        for (int p = 0; p < 8; p++) acc2[i][p] = 0ull;

    for (int t = blockIdx.y; t < NTILES; t += NCH) {
        const int n0 = t << 6;
        __syncthreads();   // protect previous tile's smem use

        // x tile (transposed) — pad rows beyond N with 0 (w forced to 0 via xs=1e30)
        #pragma unroll
        for (int i = 0; i < 16; i++) {
            int e = tid + i * 256;
            int r = e >> 6, d = e & 63;
            int n = n0 + r;
            xt[d][r] = (n < N_TOTAL) ? dataset[(size_t)n * D_DIM + d] : 0.f;
        }
        // alpha tile [n][f]
        #pragma unroll
        for (int i = 0; i < 4; i++) {
            int e = tid + i * 256;
            int r = e >> 4, f = e & 15;
            int n = n0 + r;
            at[r][f] = (n < N_TOTAL) ? alpha[(size_t)n * F_DIM + f] : 0.f;
        }
        if (tid < 64) {
            int n = n0 + tid;
            xs_s[tid] = (n < N_TOTAL) ? g_xsqs[n] : 1e30f;  // pad -> exp2f(-inf)=0
        }
        __syncthreads();

        // ---- cross = z . x^T  (packed f32x2 along the n dimension) ----
        u64 c2[4][2];
        #pragma unroll
        for (int i = 0; i < 4; i++) { c2[i][0] = 0ull; c2[i][1] = 0ull; }

        #pragma unroll 8
        for (int d = 0; d < D_DIM; d++) {
            u64 rx0 = *(const u64*)&xt[d][tx * 4];       // (x[n0j],x[n0j+1])
            u64 rx1 = *(const u64*)&xt[d][tx * 4 + 2];   // (x[n0j+2],x[n0j+3])
            #pragma unroll
            for (int i = 0; i < 4; i++) {
                float zv = zt[d][ty * 4 + i];
                u64 z2 = pack2(zv, zv);
                c2[i][0] = fma2(z2, rx0, c2[i][0]);
                c2[i][1] = fma2(z2, rx1, c2[i][1]);
            }
        }

        // ---- weights: w = exp2(cross*log2e - zs - xs) ----
        float zc[4], xc[4];
        #pragma unroll
        for (int i = 0; i < 4; i++) zc[i] = zs_s[ty * 4 + i];
        #pragma unroll
        for (int j = 0; j < 4; j++) xc[j] = xs_s[tx * 4 + j];

        float w[4][4];
        #pragma unroll
        for (int i = 0; i < 4; i++) {
            #pragma unroll
            for (int p = 0; p < 2; p++) {
                float clo, chi;
                unpack2(c2[i][p], clo, chi);
                w[i][2 * p]     = exp2f(fmaf(clo, 1.4426950408889634f, -(zc[i] + xc[2 * p])));
                w[i][2 * p + 1] = exp2f(fmaf(chi, 1.4426950408889634f, -(zc[i] + xc[2 * p + 1])));
            }
        }

        // ---- accumulate out += w * alpha (packed f32x2 along f) ----
        #pragma unroll
        for (int j = 0; j < 4; j++) {
            const int n = tx * 4 + j;
            u64 wp[4];
            #pragma unroll
            for (int i = 0; i < 4; i++) wp[i] = pack2(w[i][j], w[i][j]);
            #pragma unroll
            for (int p = 0; p < 8; p++) {
                u64 ap = *(const u64*)&at[n][2 * p];
                #pragma unroll
                for (int i = 0; i < 4; i++)
                    acc2[i][p] = fma2(wp[i], ap, acc2[i][p]);
            }
        }
    }

    // ---- reduce across the 16 tx lanes (within half-warp) ----
    // lane = (ty&1)*16 + tx, so xor masks {8,4,2,1} stay inside a tx group.
    float* part = g_part + (size_t)blockIdx.y * (B_TOTAL * F_DIM);
    #pragma unroll
    for (int i = 0; i < 4; i++) {
        #pragma unroll
        for (int p = 0; p < 8; p++) {
            float vlo, vhi;
            unpack2(acc2[i][p], vlo, vhi);
            #pragma unroll
            for (int o = 8; o; o >>= 1) {
                vlo += __shfl_xor_sync(0xffffffffu, vlo, o);
                vhi += __shfl_xor_sync(0xffffffffu, vhi, o);
            }
            if (tx == 0) {
                int b = b0 + ty * 4 + i;
                part[b * F_DIM + 2 * p]     = vlo;
                part[b * F_DIM + 2 * p + 1] = vhi;
            }
        }
    }
}

// Deterministic final reduction over the NCH partial buffers.
__global__ void rbf_reduce(float* __restrict__ out) {
    int gid = blockIdx.x * blockDim.x + threadIdx.x;
    if (gid >= B_TOTAL * F_DIM) return;
    float s = 0.f;
    #pragma unroll
    for (int c = 0; c < NCH; c++) s += g_part[c * (B_TOTAL * F_DIM) + gid];
    out[gid] = s;
}

extern "C" void kernel_launch(void* const* d_in, const int* in_sizes, int n_in,
                              void* d_out, int out_size) {
    const float* z       = (const float*)d_in[0];   // [2048, 64]
    const float* dataset = (const float*)d_in[1];   // [100000, 64]
    const float* alpha   = (const float*)d_in[2];   // [100000, 16]
    float* out = (float*)d_out;                     // [2048, 16]

    (void)in_sizes; (void)n_in; (void)out_size;

    const int rows = N_TOTAL + B_TOTAL;                 // one warp per row
    rbf_pre<<<(rows * 32 + 255) / 256, 256>>>(z, dataset);

    dim3 grid(B_TOTAL / 64, NCH);
    rbf_main<<<grid, 256>>>(z, dataset, alpha);

    rbf_reduce<<<(B_TOTAL * F_DIM + 255) / 256, 256>>>(out);
}